// round 6
// baseline (speedup 1.0000x reference)
#include <cuda_runtime.h>
#include <math.h>

// ---------------------------------------------------------------------------
// SpSpMM: C[n,n] = A @ B, COO inputs (duplicates sum), dense f32 output.
//
// ONE persistent kernel (each launch costs ~3.5us; build work is only ~2.5us):
//   phase 1 : bucket A by row i, B by row k (grid-stride, global atomics)
//   barrier : software grid barrier. 592 CTAs (4/SM) are guaranteed
//             co-resident (smem 16KB -> occ limit 8/SM). Race-free reset via
//             separate arrive/depart counters; spin is BOUNDED so a failure
//             mode is a wrong answer, never a container hang.
//   phase 2 : per-row SMEM accumulation, byte-exact R2 inner loop (fastest
//             measured: 28.8us), grid-stride over rows, coalesced writeout.
//   tail    : last CTA (completion counter) re-zeroes cnt arrays for the
//             next graph replay. Module zero-init covers call #1.
// ---------------------------------------------------------------------------

#define N_MAX   4096
#define CAP     256          // per-bucket capacity (mean 32; overflow ~impossible)
#define NTHR    256
#define GRID    592          // 4 CTAs/SM * 148 SMs, co-resident by occupancy

__device__ int      g_cntA[N_MAX];
__device__ int      g_cntB[N_MAX];
__device__ int      g_kA[N_MAX * CAP];     // col k of A entry in row i
__device__ float    g_vA[N_MAX * CAP];
__device__ int      g_cB[N_MAX * CAP];     // col j of B entry in row k
__device__ float    g_vB[N_MAX * CAP];
__device__ unsigned g_arrive = 0;          // barrier arrivals
__device__ unsigned g_depart = 0;          // barrier departures (safe reset)
__device__ unsigned g_done   = 0;          // completion counter (state reset)

__global__ void __launch_bounds__(NTHR)
spspmm_kernel(const int* __restrict__ a_idx, const float* __restrict__ a_val,
              int nnzA,
              const int* __restrict__ b_idx, const float* __restrict__ b_val,
              int nnzB,
              float* __restrict__ C, int n) {
    __shared__ float acc[N_MAX];           // 16 KB row accumulator
    __shared__ int   s_last;

    int tid  = threadIdx.x;
    int lane = tid & 31;
    int warp = tid >> 5;                   // 0..7

    // ---------------- phase 1: bucketing (grid-stride) ----------------------
    int total  = nnzA + nnzB;
    int stride = gridDim.x * NTHR;
    for (int t = blockIdx.x * NTHR + tid; t < total; t += stride) {
        if (t < nnzA) {
            int i = a_idx[t];
            int k = a_idx[nnzA + t];
            if ((unsigned)i < (unsigned)n) {
                int slot = atomicAdd(&g_cntA[i], 1);
                if (slot < CAP) {
                    g_kA[i * CAP + slot] = k;
                    g_vA[i * CAP + slot] = a_val[t];
                }
            }
        } else {
            int u = t - nnzA;
            int k = b_idx[u];
            int j = b_idx[nnzB + u];
            if ((unsigned)k < (unsigned)n) {
                int slot = atomicAdd(&g_cntB[k], 1);
                if (slot < CAP) {
                    g_cB[k * CAP + slot] = j;
                    g_vB[k * CAP + slot] = b_val[u];
                }
            }
        }
    }

    // zero the SMEM accumulator while other CTAs finish phase 1
    float4* acc4 = reinterpret_cast<float4*>(acc);
    #pragma unroll
    for (int t = tid; t < N_MAX / 4; t += NTHR)
        acc4[t] = make_float4(0.f, 0.f, 0.f, 0.f);

    // ---------------- grid barrier (race-free, bounded) ---------------------
    __threadfence();                       // publish this thread's bucket writes
    __syncthreads();                       // whole CTA past phase 1 + fences
    if (tid == 0) {
        atomicAdd(&g_arrive, 1u);
        unsigned spins = 0;
        while (atomicAdd(&g_arrive, 0u) < (unsigned)gridDim.x &&
               ++spins < (1u << 24))       // bounded: cannot hang the container
            __nanosleep(32);
        // departure phase: the LAST departer has proof everyone left the spin,
        // so it can reset both counters without racing a poller.
        unsigned d = atomicAdd(&g_depart, 1u);
        if (d == (unsigned)gridDim.x - 1u) {
            g_arrive = 0;
            g_depart = 0;
            __threadfence();
        }
    }
    __syncthreads();                       // release whole CTA

    // ---------------- phase 2: per-row products (grid-stride) ---------------
    // Inner loop is byte-exact R2 (fastest measured form).
    for (int i = blockIdx.x; i < n; i += gridDim.x) {
        int cA = min(g_cntA[i], CAP);

        for (int ia = warp; ia < cA; ia += NTHR / 32) {
            int   k  = g_kA[i * CAP + ia];
            float av = g_vA[i * CAP + ia];
            int   cB = min(g_cntB[k], CAP);
            const int*   cb = &g_cB[k * CAP];
            const float* vb = &g_vB[k * CAP];
            for (int jb = lane; jb < cB; jb += 32) {
                atomicAdd(&acc[cb[jb]], av * vb[jb]);
            }
        }
        __syncthreads();                   // all shared atomics for row i done

        // coalesced writeout + re-zero for the next row
        float4* out4 = reinterpret_cast<float4*>(C + (long long)i * n);
        #pragma unroll
        for (int t = tid; t < N_MAX / 4; t += NTHR) {
            out4[t] = acc4[t];
            acc4[t] = make_float4(0.f, 0.f, 0.f, 0.f);
        }
        __syncthreads();                   // acc clean before next row
    }

    // ---------------- tail: state reset for the next replay -----------------
    if (tid == 0) {
        unsigned prev = atomicAdd(&g_done, 1u);
        s_last = (prev == (unsigned)(gridDim.x - 1));
    }
    __syncthreads();
    if (s_last) {
        for (int t = tid; t < n; t += NTHR) {
            g_cntA[t] = 0;
            g_cntB[t] = 0;
        }
        __syncthreads();
        if (tid == 0) {
            g_done = 0;
            __threadfence();
        }
    }
}

// ---------------------------------------------------------------------------
// Host launcher (graph-capturable: one kernel launch)
// ---------------------------------------------------------------------------
extern "C" void kernel_launch(void* const* d_in, const int* in_sizes, int n_in,
                              void* d_out, int out_size) {
    const int*   a_idx = (const int*)  d_in[0];   // [2, NNZA]
    const float* a_val = (const float*)d_in[1];   // [NNZA]
    const int*   b_idx = (const int*)  d_in[2];   // [2, NNZB]
    const float* b_val = (const float*)d_in[3];   // [NNZB]
    float*       C     = (float*)d_out;

    int nnzA = in_sizes[1];
    int nnzB = in_sizes[3];
    int N    = (int)(sqrt((double)out_size) + 0.5);   // 4096

    spspmm_kernel<<<GRID, NTHR>>>(a_idx, a_val, nnzA,
                                  b_idx, b_val, nnzB, C, N);
}

// round 7
// speedup vs baseline: 1.3144x; 1.3144x over previous
#include <cuda_runtime.h>
#include <math.h>

// ---------------------------------------------------------------------------
// SpSpMM: C[n,n] = A @ B, COO inputs (duplicates sum), dense f32 output.
//
// Two launches:
//   K1 fused_build : bucket A by row i and B by row k.
//   K2 row_product : one CTA per row (4096 CTAs — measured fastest shape;
//                    persistent/592-CTA variant was 1.8x slower), SMEM row
//                    accumulator + shared atomics (ATOMS floor ~2 cyc/lane),
//                    coalesced float4 writeout.
//                    Reset tail is FENCE-FREE: each CTA's counter reads are
//                    consumed before it increments g_done (program order), so
//                    the last CTA can zero the counters with plain stores;
//                    kernel-boundary ordering makes them visible to the next
//                    replay's build kernel. (R5 showed a __threadfence here
//                    costs ~5us by draining 16KB of STGs per CTA.)
// ---------------------------------------------------------------------------

#define N_MAX 4096
#define CAP   256      // per-bucket capacity (mean 32; overflow prob ~ 0)

__device__ int      g_cntA[N_MAX];          // entries of A in row i
__device__ int      g_cntB[N_MAX];          // entries of B in row k
__device__ int      g_kA[N_MAX * CAP];      // col k of A entry in row i
__device__ float    g_vA[N_MAX * CAP];
__device__ int      g_cB[N_MAX * CAP];      // col j of B entry in row k
__device__ float    g_vB[N_MAX * CAP];
__device__ unsigned g_done = 0;             // CTA completion counter (reset)

// ---------------------------------------------------------------------------
// K1: fused bucketing. Threads [0,nnzA) handle A, [nnzA, nnzA+nnzB) handle B.
//     idx layout [2, nnz]: idx[t]=row, idx[nnz+t]=col.
// ---------------------------------------------------------------------------
__global__ void fused_build_kernel(const int* __restrict__ a_idx,
                                   const float* __restrict__ a_val, int nnzA,
                                   const int* __restrict__ b_idx,
                                   const float* __restrict__ b_val, int nnzB,
                                   int n) {
    int t = blockIdx.x * blockDim.x + threadIdx.x;
    if (t < nnzA) {
        int i = a_idx[t];
        int k = a_idx[nnzA + t];
        if ((unsigned)i < (unsigned)n) {
            int slot = atomicAdd(&g_cntA[i], 1);
            if (slot < CAP) {
                g_kA[i * CAP + slot] = k;
                g_vA[i * CAP + slot] = a_val[t];
            }
        }
    } else {
        int u = t - nnzA;
        if (u < nnzB) {
            int k = b_idx[u];
            int j = b_idx[nnzB + u];
            if ((unsigned)k < (unsigned)n) {
                int slot = atomicAdd(&g_cntB[k], 1);
                if (slot < CAP) {
                    g_cB[k * CAP + slot] = j;
                    g_vB[k * CAP + slot] = b_val[u];
                }
            }
        }
    }
}

// ---------------------------------------------------------------------------
// K2: one CTA per output row i.  (Inner loop byte-exact = R2's 28.8us form.)
// ---------------------------------------------------------------------------
#define ROW_THREADS 256

__global__ void __launch_bounds__(ROW_THREADS)
row_product_kernel(float* __restrict__ C, int n) {
    int i = blockIdx.x;

    __shared__ float acc[N_MAX];         // 16 KB row accumulator
    __shared__ int   s_last;

    int tid  = threadIdx.x;
    int lane = tid & 31;
    int warp = tid >> 5;                  // 0..7

    // zero accumulator (vectorized)
    float4* acc4 = reinterpret_cast<float4*>(acc);
    #pragma unroll
    for (int t = tid; t < N_MAX / 4; t += ROW_THREADS)
        acc4[t] = make_float4(0.f, 0.f, 0.f, 0.f);
    __syncthreads();

    int cA = min(g_cntA[i], CAP);

    // each warp takes A entries round-robin; lanes stride the B bucket
    for (int ia = warp; ia < cA; ia += ROW_THREADS / 32) {
        int   k  = g_kA[i * CAP + ia];
        float av = g_vA[i * CAP + ia];
        int   cB = min(g_cntB[k], CAP);
        const int*   cb = &g_cB[k * CAP];
        const float* vb = &g_vB[k * CAP];
        for (int jb = lane; jb < cB; jb += 32) {
            atomicAdd(&acc[cb[jb]], av * vb[jb]);
        }
    }
    __syncthreads();

    // stream out the finished row, fully coalesced
    float4* out4 = reinterpret_cast<float4*>(C + (long long)i * n);
    #pragma unroll
    for (int t = tid; t < N_MAX / 4; t += ROW_THREADS)
        out4[t] = acc4[t];

    // ---- fence-free counter reset by the last CTA to finish ----
    // All counter reads in this CTA precede this atomic in program order and
    // have been consumed; the last CTA therefore zeroes safely. Visibility to
    // the next launch is provided by the kernel boundary.
    if (tid == 0) {
        unsigned prev = atomicAdd(&g_done, 1u);
        s_last = (prev == (unsigned)(gridDim.x - 1));
    }
    __syncthreads();
    if (s_last) {
        for (int t = tid; t < n; t += ROW_THREADS) {
            g_cntA[t] = 0;
            g_cntB[t] = 0;
        }
        if (tid == 0) g_done = 0;
    }
}

// ---------------------------------------------------------------------------
// Host launcher (graph-capturable: two kernel launches)
// ---------------------------------------------------------------------------
extern "C" void kernel_launch(void* const* d_in, const int* in_sizes, int n_in,
                              void* d_out, int out_size) {
    const int*   a_idx = (const int*)  d_in[0];   // [2, NNZA]
    const float* a_val = (const float*)d_in[1];   // [NNZA]
    const int*   b_idx = (const int*)  d_in[2];   // [2, NNZB]
    const float* b_val = (const float*)d_in[3];   // [NNZB]
    float*       C     = (float*)d_out;

    int nnzA = in_sizes[1];
    int nnzB = in_sizes[3];
    int N    = (int)(sqrt((double)out_size) + 0.5);   // 4096

    int total = nnzA + nnzB;
    fused_build_kernel<<<(total + 255) / 256, 256>>>(a_idx, a_val, nnzA,
                                                     b_idx, b_val, nnzB, N);
    row_product_kernel<<<N, ROW_THREADS>>>(C, N);
}